// round 5
// baseline (speedup 1.0000x reference)
#include <cuda_runtime.h>
#include <cstdint>

#define Kc   10
#define Hc   224
#define Wc   224
#define BNc  16
#define Tc   15
#define PADc 7
#define SHc  7                  // strip height (224 = 32*7)
#define NSTRIP (Hc/SHc)         // 32
#define AS_W 239                // W + 2*PAD = 238, +1
#define AS_H (SHc + 2*PADc)     // 21
#define AS_CH (AS_H*AS_W)       // 5019 floats per channel
#define AS_TOTAL_PAD 50192      // 10*AS_CH = 50190, padded to 16B multiple
#define NXQ (Wc/4)              // 56 groups of 4 pixels
#define BS_STRIDE (NXQ*5*4)     // floats per yy row in Bs: 56*20 = 1120
#define BS_TOTAL (SHc*BS_STRIDE) // 7840 floats
#define NSH (Tc*Tc)             // 225
#define EPSF 1e-16f
#define SMEM_BYTES ((AS_TOTAL_PAD + BS_TOTAL)*4)   // 232,128 B

__device__ float g_p[NSH*Kc*Kc];   // joint histogram; zero at module load,
                                   // re-zeroed by loss_kernel each iteration.

// One block = (y-strip, batch). 512 threads: tid<256 -> n-half 0, tid>=256 -> n-half 1.
// Thread t (s = t&255 < 225) owns shift (sy,sx)=s and accumulates 5(n) x 5(o)
// packed f32x2 sums for the o-half given by `oh`.
__global__ __launch_bounds__(512, 1)
void hist_kernel(const float* __restrict__ xo, const float* __restrict__ xt, int oh) {
    extern __shared__ float sm[];
    float* As = sm;                    // [10][AS_H][AS_W] Xo strip + halo (zero pad)
    float* Bs = sm + AS_TOTAL_PAD;     // [SHc][NXQ][5][4] Xt strip, interleaved

    const int strip = blockIdx.x;
    const int c     = blockIdx.y;
    const int y0    = strip * SHc;
    const int tid   = threadIdx.x;

    // ---- cooperative load: Xo (all 10 channels) with halo ----
    const float* xoc = xo + (size_t)c * Kc * Hc * Wc;
    for (int e = tid; e < Kc*AS_CH; e += 512) {
        int n  = e / AS_CH;
        int r  = (e % AS_CH) / AS_W;
        int ax = e % AS_W;
        int gy = y0 + r - PADc;
        int gx = ax - PADc;
        float v = 0.0f;
        if ((unsigned)gy < (unsigned)Hc && (unsigned)gx < (unsigned)Wc)
            v = xoc[(n*Hc + gy)*Wc + gx];
        As[e] = v;
    }
    // ---- cooperative load: Xt strip (5 o-channels), interleaved [yy][xq][j][4] ----
    const float* xtc = xt + (size_t)c * Kc * Hc * Wc + (size_t)oh * 5 * Hc * Wc;
    for (int e = tid; e < 5*SHc*Wc; e += 512) {
        int j  = e / (SHc*Wc);
        int rr = e % (SHc*Wc);
        int yy = rr / Wc;
        int x  = rr % Wc;
        Bs[yy*BS_STRIDE + (x >> 2)*20 + j*4 + (x & 3)] = xtc[j*Hc*Wc + y0*Wc + rr];
    }
    __syncthreads();

    const int s  = tid & 255;
    const int nh = tid >> 8;
    if (s >= NSH) return;
    const int sy  = s / Tc;
    const int sxi = s % Tc;

    unsigned long long acc[25];
    #pragma unroll
    for (int i = 0; i < 25; i++) acc[i] = 0ULL;

    const float* aBase = As + nh*5*AS_CH + sy*AS_W + sxi;

    for (int yy = 0; yy < SHc; yy++) {
        const float* aR = aBase + yy*AS_W;
        const float* bR = Bs + yy*BS_STRIDE;
        #pragma unroll 2
        for (int xq = 0; xq < NXQ; xq++) {
            // b: 5 channels x 4 px, one LDS.128 each (broadcast)
            unsigned long long b01[5], b23[5];
            #pragma unroll
            for (int j = 0; j < 5; j++) {
                float4 bv = *reinterpret_cast<const float4*>(bR + xq*20 + j*4);
                asm("mov.b64 %0, {%1, %2};" : "=l"(b01[j]) : "f"(bv.x), "f"(bv.y));
                asm("mov.b64 %0, {%1, %2};" : "=l"(b23[j]) : "f"(bv.z), "f"(bv.w));
            }
            #pragma unroll
            for (int n = 0; n < 5; n++) {
                const float* ap = aR + n*AS_CH + xq*4;
                float a0 = ap[0], a1 = ap[1], a2 = ap[2], a3 = ap[3];
                unsigned long long a01, a23;
                asm("mov.b64 %0, {%1, %2};" : "=l"(a01) : "f"(a0), "f"(a1));
                asm("mov.b64 %0, {%1, %2};" : "=l"(a23) : "f"(a2), "f"(a3));
                #pragma unroll
                for (int j = 0; j < 5; j++) {
                    asm("fma.rn.f32x2 %0, %1, %2, %0;"
                        : "+l"(acc[n*5 + j]) : "l"(a01), "l"(b01[j]));
                    asm("fma.rn.f32x2 %0, %1, %2, %0;"
                        : "+l"(acc[n*5 + j]) : "l"(a23), "l"(b23[j]));
                }
            }
        }
    }

    // ---- fold halves, accumulate into global histogram ----
    #pragma unroll
    for (int n = 0; n < 5; n++) {
        #pragma unroll
        for (int j = 0; j < 5; j++) {
            float lo, hi;
            asm("mov.b64 {%0, %1}, %2;" : "=f"(lo), "=f"(hi) : "l"(acc[n*5 + j]));
            atomicAdd(&g_p[s*100 + (nh*5 + n)*10 + (oh*5 + j)], lo + hi);
        }
    }
}

// Single block: min-shift, per-shift normalize + symmetrize, MI-style loss.
// Re-zeroes g_p afterwards so the next graph replay starts clean.
__global__ void loss_kernel(float* __restrict__ out) {
    __shared__ float red[256];
    const int t = threadIdx.x;

    float mn = 3.4e38f;
    for (int i = t; i < NSH*100; i += 256) mn = fminf(mn, g_p[i]);
    red[t] = mn; __syncthreads();
    for (int s = 128; s > 0; s >>= 1) {
        if (t < s) red[t] = fminf(red[t], red[t + s]);
        __syncthreads();
    }
    const float pmin = red[0];
    __syncthreads();

    float loss = 0.0f;
    if (t < NSH) {
        const float* q = g_p + t*100;
        float row[10], col[10], S = 0.0f;
        #pragma unroll
        for (int i = 0; i < 10; i++) { row[i] = 0.0f; col[i] = 0.0f; }
        #pragma unroll
        for (int n = 0; n < 10; n++) {
            #pragma unroll
            for (int o = 0; o < 10; o++) {
                float v = q[n*10 + o] - pmin + EPSF;
                S += v; row[n] += v; col[o] += v;
            }
        }
        const float inv2S = 0.5f / S;
        float lp[10];
        #pragma unroll
        for (int i = 0; i < 10; i++)
            lp[i] = logf((row[i] + col[i]) * inv2S + EPSF);   // p_i == p_j by symmetry
        #pragma unroll
        for (int n = 0; n < 10; n++) {
            #pragma unroll
            for (int o = 0; o < 10; o++) {
                float v1 = q[n*10 + o] - pmin + EPSF;
                float v2 = q[o*10 + n] - pmin + EPSF;
                float pp = (v1 + v2) * inv2S;
                loss -= pp * (logf(pp + EPSF) - lp[o] - lp[n]);
            }
        }
    }
    red[t] = loss; __syncthreads();
    // all reads of g_p are complete (every thread wrote red[t]); re-zero now
    for (int i = t; i < NSH*100; i += 256) g_p[i] = 0.0f;
    for (int s = 128; s > 0; s >>= 1) {
        if (t < s) red[t] += red[t + s];
        __syncthreads();
    }
    if (t == 0) out[0] = red[0] / (float)NSH;
}

extern "C" void kernel_launch(void* const* d_in, const int* in_sizes, int n_in,
                              void* d_out, int out_size) {
    const float* xo = (const float*)d_in[0];   // x_out    (16,10,224,224) f32
    const float* xt = (const float*)d_in[1];   // x_tf_out (16,10,224,224) f32
    float* out = (float*)d_out;

    cudaFuncSetAttribute(hist_kernel, cudaFuncAttributeMaxDynamicSharedMemorySize, SMEM_BYTES);

    dim3 grid(NSTRIP, BNc, 1);
    hist_kernel<<<grid, 512, SMEM_BYTES>>>(xo, xt, 0);
    hist_kernel<<<grid, 512, SMEM_BYTES>>>(xo, xt, 1);
    loss_kernel<<<1, 256>>>(out);
}

// round 7
// speedup vs baseline: 1.2107x; 1.2107x over previous
#include <cuda_runtime.h>
#include <cstdint>

#define Kc   10
#define Hc   224
#define Wc   224
#define BNc  16
#define Tc   15
#define PADc 7
#define SHc  8                   // strip height (224 = 28*8)
#define NSTRIP (Hc/SHc)          // 28
#define AS_W 239                 // 238 needed; 239 -> conflict-free (239 mod 32 = 15)
#define AS_H (SHc + 2*PADc)      // 22
#define AS_CH (AS_H*AS_W)        // 5258 floats per channel
#define NCH_A 5                  // channels of A per block (n-half)
#define AS_PAD 26292             // 5*AS_CH = 26290, padded so Bs is 16B-aligned
#define NXQ (Wc/4)               // 56 pixel-quads per row
#define BS_STRIDE (NXQ*Kc*4)     // 2240 floats per yy row: [xq][j=10][4px]
#define BS_TOTAL (SHc*BS_STRIDE) // 17920 floats
#define NSH (Tc*Tc)              // 225
#define EPSF 1e-16f
#define SMEM_BYTES ((AS_PAD + BS_TOTAL)*4)   // (26292+17920)*4 = 176,848 B

__device__ float g_p[NSH*Kc*Kc];   // joint histogram; zero at module load,
                                   // re-zeroed by loss_kernel each iteration.

// One block = (y-strip, batch, n-half). 256 threads.
// Threads 0..223: shift s = tid, accumulate 5(n) x 10(o) f32x2 pixel-pair sums.
// Warp 7 (tid 224..255): shift s = 224 cooperatively, lanes split pixel-quads.
__global__ __launch_bounds__(256, 1)
void hist_kernel(const float* __restrict__ xo, const float* __restrict__ xt) {
    extern __shared__ float sm[];
    float* As = sm;                    // [5][AS_H][AS_W] Xo strip + halo (zero pad)
    float* Bs = sm + AS_PAD;           // [SHc][NXQ][10][4] Xt strip, interleaved (16B-aligned)

    const int strip = blockIdx.x;
    const int c     = blockIdx.y;
    const int nh    = blockIdx.z;
    const int y0    = strip * SHc;
    const int tid   = threadIdx.x;

    // ---- cooperative load: Xo (5 channels of this n-half) with halo ----
    const float* xoc = xo + (size_t)c * Kc * Hc * Wc + (size_t)nh * NCH_A * Hc * Wc;
    for (int e = tid; e < NCH_A*AS_CH; e += 256) {
        int n  = e / AS_CH;
        int r  = (e % AS_CH) / AS_W;
        int ax = e % AS_W;
        int gy = y0 + r - PADc;
        int gx = ax - PADc;
        float v = 0.0f;
        if ((unsigned)gy < (unsigned)Hc && (unsigned)gx < (unsigned)Wc)
            v = xoc[(n*Hc + gy)*Wc + gx];
        As[e] = v;
    }
    // ---- cooperative load: Xt strip (all 10 o-channels), interleaved [yy][xq][j][4] ----
    const float* xtc = xt + (size_t)c * Kc * Hc * Wc;
    for (int e = tid; e < Kc*SHc*Wc; e += 256) {
        int j  = e / (SHc*Wc);
        int rr = e % (SHc*Wc);
        int yy = rr / Wc;
        int x  = rr % Wc;
        Bs[yy*BS_STRIDE + (x >> 2)*(Kc*4) + j*4 + (x & 3)] = xtc[j*Hc*Wc + (y0+yy)*Wc + x];
    }
    __syncthreads();

    const int lane = tid & 31;

    unsigned long long acc[50];
    #pragma unroll
    for (int i = 0; i < 50; i++) acc[i] = 0ULL;

    if (tid < 224) {
        // ---- standard path: one shift per thread ----
        const int s   = tid;
        const int sy  = s / Tc;
        const int sxi = s % Tc;
        const float* aBase = As + sy*AS_W + sxi;

        for (int yy = 0; yy < SHc; yy++) {
            const float* aR = aBase + yy*AS_W;
            const float* bR = Bs + yy*BS_STRIDE;
            #pragma unroll 2
            for (int xq = 0; xq < NXQ; xq++) {
                // a: 5 channels x 4 px (scalar LDS, conflict-free; packed to f32x2)
                unsigned long long a01[5], a23[5];
                #pragma unroll
                for (int n = 0; n < 5; n++) {
                    const float* ap = aR + n*AS_CH + xq*4;
                    float x0 = ap[0], x1 = ap[1], x2 = ap[2], x3 = ap[3];
                    asm("mov.b64 %0, {%1, %2};" : "=l"(a01[n]) : "f"(x0), "f"(x1));
                    asm("mov.b64 %0, {%1, %2};" : "=l"(a23[n]) : "f"(x2), "f"(x3));
                }
                #pragma unroll
                for (int j = 0; j < 10; j++) {
                    float4 bv = *reinterpret_cast<const float4*>(bR + xq*(Kc*4) + j*4);
                    unsigned long long b01, b23;
                    asm("mov.b64 %0, {%1, %2};" : "=l"(b01) : "f"(bv.x), "f"(bv.y));
                    asm("mov.b64 %0, {%1, %2};" : "=l"(b23) : "f"(bv.z), "f"(bv.w));
                    #pragma unroll
                    for (int n = 0; n < 5; n++) {
                        asm("fma.rn.f32x2 %0, %1, %2, %0;"
                            : "+l"(acc[n*10 + j]) : "l"(a01[n]), "l"(b01));
                        asm("fma.rn.f32x2 %0, %1, %2, %0;"
                            : "+l"(acc[n*10 + j]) : "l"(a23[n]), "l"(b23));
                    }
                }
            }
        }

        #pragma unroll
        for (int n = 0; n < 5; n++) {
            #pragma unroll
            for (int j = 0; j < 10; j++) {
                float lo, hi;
                asm("mov.b64 {%0, %1}, %2;" : "=f"(lo), "=f"(hi) : "l"(acc[n*10 + j]));
                atomicAdd(&g_p[s*100 + (nh*5 + n)*10 + j], lo + hi);
            }
        }
    } else {
        // ---- warp 7: shift s=224 (sy=14,sx=14), lanes split pixel-quads ----
        const float* aBase = As + 14*AS_W + 14;
        for (int yy = 0; yy < SHc; yy++) {
            const float* aR = aBase + yy*AS_W;
            const float* bR = Bs + yy*BS_STRIDE;
            for (int xq = lane; xq < NXQ; xq += 32) {
                unsigned long long a01[5], a23[5];
                #pragma unroll
                for (int n = 0; n < 5; n++) {
                    const float* ap = aR + n*AS_CH + xq*4;
                    float x0 = ap[0], x1 = ap[1], x2 = ap[2], x3 = ap[3];
                    asm("mov.b64 %0, {%1, %2};" : "=l"(a01[n]) : "f"(x0), "f"(x1));
                    asm("mov.b64 %0, {%1, %2};" : "=l"(a23[n]) : "f"(x2), "f"(x3));
                }
                #pragma unroll
                for (int j = 0; j < 10; j++) {
                    float4 bv = *reinterpret_cast<const float4*>(bR + xq*(Kc*4) + j*4);
                    unsigned long long b01, b23;
                    asm("mov.b64 %0, {%1, %2};" : "=l"(b01) : "f"(bv.x), "f"(bv.y));
                    asm("mov.b64 %0, {%1, %2};" : "=l"(b23) : "f"(bv.z), "f"(bv.w));
                    #pragma unroll
                    for (int n = 0; n < 5; n++) {
                        asm("fma.rn.f32x2 %0, %1, %2, %0;"
                            : "+l"(acc[n*10 + j]) : "l"(a01[n]), "l"(b01));
                        asm("fma.rn.f32x2 %0, %1, %2, %0;"
                            : "+l"(acc[n*10 + j]) : "l"(a23[n]), "l"(b23));
                    }
                }
            }
        }
        // warp-reduce the 50 accumulators, lane 0 commits
        #pragma unroll
        for (int i = 0; i < 50; i++) {
            float lo, hi;
            asm("mov.b64 {%0, %1}, %2;" : "=f"(lo), "=f"(hi) : "l"(acc[i]));
            float v = lo + hi;
            #pragma unroll
            for (int o = 16; o > 0; o >>= 1)
                v += __shfl_down_sync(0xFFFFFFFFu, v, o);
            if (lane == 0) {
                int n = i / 10, j = i % 10;
                atomicAdd(&g_p[224*100 + (nh*5 + n)*10 + j], v);
            }
        }
    }
}

// Single block: min-shift, per-shift normalize + symmetrize, MI-style loss.
// Re-zeroes g_p afterwards so the next graph replay starts clean.
__global__ void loss_kernel(float* __restrict__ out) {
    __shared__ float red[256];
    const int t = threadIdx.x;

    float mn = 3.4e38f;
    for (int i = t; i < NSH*100; i += 256) mn = fminf(mn, g_p[i]);
    red[t] = mn; __syncthreads();
    for (int s = 128; s > 0; s >>= 1) {
        if (t < s) red[t] = fminf(red[t], red[t + s]);
        __syncthreads();
    }
    const float pmin = red[0];
    __syncthreads();

    float loss = 0.0f;
    if (t < NSH) {
        const float* q = g_p + t*100;
        float row[10], col[10], S = 0.0f;
        #pragma unroll
        for (int i = 0; i < 10; i++) { row[i] = 0.0f; col[i] = 0.0f; }
        #pragma unroll
        for (int n = 0; n < 10; n++) {
            #pragma unroll
            for (int o = 0; o < 10; o++) {
                float v = q[n*10 + o] - pmin + EPSF;
                S += v; row[n] += v; col[o] += v;
            }
        }
        const float inv2S = 0.5f / S;
        float lp[10];
        #pragma unroll
        for (int i = 0; i < 10; i++)
            lp[i] = logf((row[i] + col[i]) * inv2S + EPSF);   // p_i == p_j by symmetry
        #pragma unroll
        for (int n = 0; n < 10; n++) {
            #pragma unroll
            for (int o = 0; o < 10; o++) {
                float v1 = q[n*10 + o] - pmin + EPSF;
                float v2 = q[o*10 + n] - pmin + EPSF;
                float pp = (v1 + v2) * inv2S;
                loss -= pp * (logf(pp + EPSF) - lp[o] - lp[n]);
            }
        }
    }
    red[t] = loss; __syncthreads();
    // all reads of g_p are complete (every thread wrote red[t]); re-zero now
    for (int i = t; i < NSH*100; i += 256) g_p[i] = 0.0f;
    for (int s = 128; s > 0; s >>= 1) {
        if (t < s) red[t] += red[t + s];
        __syncthreads();
    }
    if (t == 0) out[0] = red[0] / (float)NSH;
}

extern "C" void kernel_launch(void* const* d_in, const int* in_sizes, int n_in,
                              void* d_out, int out_size) {
    const float* xo = (const float*)d_in[0];   // x_out    (16,10,224,224) f32
    const float* xt = (const float*)d_in[1];   // x_tf_out (16,10,224,224) f32
    float* out = (float*)d_out;

    cudaFuncSetAttribute(hist_kernel, cudaFuncAttributeMaxDynamicSharedMemorySize, SMEM_BYTES);

    dim3 grid(NSTRIP, BNc, 2);
    hist_kernel<<<grid, 256, SMEM_BYTES>>>(xo, xt);
    loss_kernel<<<1, 256>>>(out);
}